// round 2
// baseline (speedup 1.0000x reference)
#include <cuda_runtime.h>

// Problem constants
#define C_IN   384
#define NQKV   1152
#define MROWS  65536        // 1024 windows * 64 tokens
#define SHIFT_ 4

// Scratch (device globals; no allocation in kernel_launch)
__device__ float g_qkv[(size_t)MROWS * NQKV];   // 302 MB
__device__ float g_att[(size_t)MROWS * C_IN];   // 100 MB

// Map flattened window-token row m -> pixel base offset in the (B,64,64,384)
// image, applying the cyclic shift. Works for BOTH the input gather (roll by
// -SHIFT then window) and the output scatter (un-window then roll by +SHIFT):
// both map window coordinate (wh*8+i, ww*8+j) <-> pixel ((wh*8+i+SHIFT)%64, ...).
__device__ __forceinline__ int pix_base(int m) {
    int w  = m >> 6;        // window id: b*64 + wh*8 + ww
    int t  = m & 63;        // token id:  i*8 + j
    int b  = w >> 6;
    int wh = (w >> 3) & 7;
    int ww = w & 7;
    int i  = t >> 3;
    int j  = t & 7;
    int r  = (wh * 8 + i + SHIFT_) & 63;
    int c  = (ww * 8 + j + SHIFT_) & 63;
    return ((b * 64 + r) * 64 + c) * C_IN;
}

// 128x128x8 fp32 GEMM, 256 threads, 8x8 microtile per thread.
// GATHER: A rows gathered from the rolled/windowed input image.
// SCATTER: output rows scattered back to image layout (un-roll).
template<int N, bool GATHER, bool SCATTER>
__global__ __launch_bounds__(256) void gemm_kernel(const float* __restrict__ X,
                                                   const float* __restrict__ W,
                                                   const float* __restrict__ bias,
                                                   float* __restrict__ Y)
{
    __shared__ float As[8][128];
    __shared__ float Bs[8][132];   // +4 pad
    __shared__ int   rowBase[128];

    const int tid = threadIdx.x;
    const int m0  = blockIdx.y * 128;
    const int n0  = blockIdx.x * 128;

    if (tid < 128) {
        int m = m0 + tid;
        rowBase[tid] = GATHER ? pix_base(m) : m * C_IN;
    }
    __syncthreads();

    const float* Asrc = GATHER ? X : g_att;
    float*       Ydst = SCATTER ? Y : g_qkv;

    const int tr = tid >> 4, tc = tid & 15;          // 16x16 thread grid
    const int aRow = tid >> 1, aCol = (tid & 1) * 4; // A tile loaders
    const int bRow = tid >> 5, bCol = (tid & 31) * 4;

    float acc[8][8];
    #pragma unroll
    for (int u = 0; u < 8; u++)
        #pragma unroll
        for (int v = 0; v < 8; v++) acc[u][v] = 0.f;

    for (int k0 = 0; k0 < C_IN; k0 += 8) {
        float4 av = *(const float4*)(Asrc + rowBase[aRow] + k0 + aCol);
        As[aCol + 0][aRow] = av.x;
        As[aCol + 1][aRow] = av.y;
        As[aCol + 2][aRow] = av.z;
        As[aCol + 3][aRow] = av.w;
        *(float4*)&Bs[bRow][bCol] =
            *(const float4*)(W + (size_t)(k0 + bRow) * N + n0 + bCol);
        __syncthreads();

        #pragma unroll
        for (int k = 0; k < 8; k++) {
            float a[8], b[8];
            #pragma unroll
            for (int u = 0; u < 8; u++) a[u] = As[k][tr * 8 + u];
            #pragma unroll
            for (int v = 0; v < 8; v++) b[v] = Bs[k][tc * 8 + v];
            #pragma unroll
            for (int u = 0; u < 8; u++)
                #pragma unroll
                for (int v = 0; v < 8; v++)
                    acc[u][v] = fmaf(a[u], b[v], acc[u][v]);
        }
        __syncthreads();
    }

    #pragma unroll
    for (int u = 0; u < 8; u++) {
        int m = m0 + tr * 8 + u;
        size_t ob = SCATTER ? (size_t)pix_base(m) : (size_t)m * N;
        #pragma unroll
        for (int v = 0; v < 8; v++) {
            int n = n0 + tc * 8 + v;
            Ydst[ob + n] = acc[u][v] + bias[n];
        }
    }
}

// One block per (head, window). 64 threads; thread t owns score row t.
// NOTE: references g_qkv / g_att directly (device globals must not be passed
// by value from host code — that was the R1 bug).
__global__ __launch_bounds__(64) void attn_kernel()
{
    const int h = blockIdx.x;   // 0..11
    const int w = blockIdx.y;   // 0..1023
    const int t = threadIdx.x;  // 0..63

    __shared__ float ks[64][33];
    __shared__ float vs[64][33];
    __shared__ float sc[64][65];

    const float* base = g_qkv + (size_t)w * 64 * NQKV;
    const int qo = h * 32;
    const int ko = 384 + h * 32;
    const int vo = 768 + h * 32;

    // cooperative coalesced K/V load
    for (int e = t; e < 64 * 32; e += 64) {
        int row = e >> 5, d = e & 31;
        ks[row][d] = base[row * NQKV + ko + d];
        vs[row][d] = base[row * NQKV + vo + d];
    }

    // q row -> registers
    float qr[32];
    #pragma unroll
    for (int d = 0; d < 32; d += 4) {
        float4 q4 = *(const float4*)(base + t * NQKV + qo + d);
        qr[d] = q4.x; qr[d+1] = q4.y; qr[d+2] = q4.z; qr[d+3] = q4.w;
    }
    __syncthreads();

    // scores row t
    for (int j = 0; j < 64; j++) {
        float s = 0.f;
        #pragma unroll
        for (int d = 0; d < 32; d++) s = fmaf(qr[d], ks[j][d], s);
        sc[t][j] = s;
    }
    __syncthreads();   // all ks reads done (ks reused as output staging later)

    // softmax over own row (scale commutes with max)
    const float scale = 0.17677669529663687f;   // 1/sqrt(32)
    float mx = -1e30f;
    for (int j = 0; j < 64; j++) mx = fmaxf(mx, sc[t][j]);
    float sum = 0.f;
    for (int j = 0; j < 64; j++) {
        float p = __expf((sc[t][j] - mx) * scale);
        sc[t][j] = p;
        sum += p;
    }
    float inv = 1.f / sum;

    // P @ V
    float acc[32];
    #pragma unroll
    for (int d = 0; d < 32; d++) acc[d] = 0.f;
    for (int j = 0; j < 64; j++) {
        float p = sc[t][j];
        #pragma unroll
        for (int d = 0; d < 32; d++) acc[d] = fmaf(p, vs[j][d], acc[d]);
    }

    // stage output in smem for coalesced global store
    #pragma unroll
    for (int d = 0; d < 32; d++) ks[t][d] = acc[d] * inv;
    __syncthreads();

    float* obase = g_att + (size_t)w * 64 * C_IN + h * 32;
    for (int e = t; e < 64 * 32; e += 64) {
        int row = e >> 5, d = e & 31;
        obase[row * C_IN + d] = ks[row][d];
    }
}

extern "C" void kernel_launch(void* const* d_in, const int* in_sizes, int n_in,
                              void* d_out, int out_size)
{
    const float* x      = (const float*)d_in[0];
    const float* w_qkv  = (const float*)d_in[1];
    const float* b_qkv  = (const float*)d_in[2];
    const float* w_proj = (const float*)d_in[3];
    const float* b_proj = (const float*)d_in[4];
    float* out = (float*)d_out;

    // Stage 1: gathered QKV GEMM  (65536 x 1152 x 384)
    dim3 g1(NQKV / 128, MROWS / 128);
    gemm_kernel<NQKV, true, false><<<g1, 256>>>(x, w_qkv, b_qkv, out);

    // Stage 2: window attention, one block per (head, window)
    attn_kernel<<<dim3(12, 1024), 64>>>();

    // Stage 3: proj GEMM with scatter (65536 x 384 x 384)
    dim3 g2(C_IN / 128, MROWS / 128);
    gemm_kernel<C_IN, false, true><<<g2, 256>>>(x, w_proj, b_proj, out);
}

// round 4
// speedup vs baseline: 1.9878x; 1.9878x over previous
#include <cuda_runtime.h>

// Problem constants
#define C_IN   384
#define NQKV   1152
#define MROWS  65536        // 1024 windows * 64 tokens
#define SHIFT_ 4

// Scratch (device globals; no allocation in kernel_launch)
__device__ float g_qkv[(size_t)MROWS * NQKV];   // 302 MB
__device__ float g_att[(size_t)MROWS * C_IN];   // 100 MB

// Map flattened window-token row m -> pixel base offset in the (B,64,64,384)
// image, applying the cyclic shift. Identical map for gather and scatter.
__device__ __forceinline__ int pix_base(int m) {
    int w  = m >> 6;        // window id: b*64 + wh*8 + ww
    int t  = m & 63;        // token id:  i*8 + j
    int b  = w >> 6;
    int wh = (w >> 3) & 7;
    int ww = w & 7;
    int i  = t >> 3;
    int j  = t & 7;
    int r  = (wh * 8 + i + SHIFT_) & 63;
    int c  = (ww * 8 + j + SHIFT_) & 63;
    return ((b * 64 + r) * 64 + c) * C_IN;
}

__device__ __forceinline__ unsigned f2tf32(float f) {
    unsigned r;
    asm("cvt.rna.tf32.f32 %0, %1;" : "=r"(r) : "f"(f));
    return r;
}

// Permuted smem layouts for direct vectorized fragment loads.
// A: per-ki region stride 1028 (1024 + 4 skew) -> no overlap.
// B: per-ki region stride 1056 (1024 + 32 max ni2-skew) -> FIX of the R3
//    overflow where ni2*2 skew bled into the next ki region.
#define A_ELEMS (4*1028 + 4)
#define B_ELEMS (4*1056)
__device__ __forceinline__ int flatA(int ki, int mi2, int lane, int slot) {
    return ki * 1028 + mi2 * 128 + lane * 4 + slot;
}
__device__ __forceinline__ int flatB(int ki, int ni2, int lane, int slot) {
    return ki * 1056 + ni2 * 66 + lane * 2 + slot;
}

// TF32 tensor-core GEMM: 128x128 tile, K-chunk 32, 256 threads, 8 warps,
// warp tile 64x32 via mma.sync.m16n8k8.tf32.
template<int N, bool GATHER, bool SCATTER>
__global__ __launch_bounds__(256, 2) void gemm_tc(const float* __restrict__ X,
                                                  const float* __restrict__ W,
                                                  const float* __restrict__ bias,
                                                  float* __restrict__ Y)
{
    __shared__ unsigned As[A_ELEMS];
    __shared__ unsigned Bs[B_ELEMS];
    __shared__ int rowBase[128];
    __shared__ int outBase[128];

    const int tid = threadIdx.x;
    const int m0  = blockIdx.y * 128;
    const int n0  = blockIdx.x * 128;

    if (tid < 128) {
        int m = m0 + tid;
        rowBase[tid] = GATHER ? pix_base(m) : m * C_IN;
        if (SCATTER) outBase[tid] = pix_base(m);
    }
    __syncthreads();

    const float* Asrc = GATHER ? X : g_att;

    const int warp = tid >> 5, lane = tid & 31;
    const int wm = warp >> 2;   // 0..1  (64-row half)
    const int wn = warp & 3;    // 0..3  (32-col quarter)

    float acc[4][4][4];
    #pragma unroll
    for (int mi = 0; mi < 4; mi++)
        #pragma unroll
        for (int ni = 0; ni < 4; ni++)
            #pragma unroll
            for (int v = 0; v < 4; v++) acc[mi][ni][v] = 0.f;

    for (int k0 = 0; k0 < C_IN; k0 += 32) {
        // ---- stage A (128 x 32), permuted for fragment loads ----
        // element (m, k): r=m&15, mi2=m>>4, ki=k>>3, kk=k&7
        //   lane = (r&7)*4 + (kk&3), slot = (r>>3) + (kk>>2)*2
        #pragma unroll
        for (int it = 0; it < 4; it++) {
            int idx = tid + it * 256;           // 0..1023
            int m   = idx >> 3;                 // 0..127
            int k4  = (idx & 7) << 2;           // 0,4,...,28
            float4 v = *(const float4*)(Asrc + rowBase[m] + k0 + k4);
            int r = m & 15, mi2 = m >> 4;
            int ki = k4 >> 3;
            int slotb = ((k4 & 7) >> 2) << 1;   // 0 or 2
            int base = flatA(ki, mi2, (r & 7) * 4, (r >> 3) + slotb);
            As[base + 0 * 4] = f2tf32(v.x);
            As[base + 1 * 4] = f2tf32(v.y);
            As[base + 2 * 4] = f2tf32(v.z);
            As[base + 3 * 4] = f2tf32(v.w);
        }
        // ---- stage B (32 x 128), permuted ----
        // element (k, n): ki=k>>3, c=k&7, ni2=n>>3, g=n&7
        //   lane = g*4 + (c&3), slot = c>>2
        #pragma unroll
        for (int it = 0; it < 4; it++) {
            int idx = tid + it * 256;           // 0..1023
            int k   = idx >> 5;                 // 0..31
            int n4  = (idx & 31) << 2;          // 0,4,...,124
            float4 v = *(const float4*)(W + (size_t)(k0 + k) * N + n0 + n4);
            int ki = k >> 3, c = k & 7;
            int ni2 = n4 >> 3;
            int base = flatB(ki, ni2, ((n4 & 7) << 2) + (c & 3), c >> 2);
            Bs[base + 0 * 8] = f2tf32(v.x);
            Bs[base + 1 * 8] = f2tf32(v.y);
            Bs[base + 2 * 8] = f2tf32(v.z);
            Bs[base + 3 * 8] = f2tf32(v.w);
        }
        __syncthreads();

        #pragma unroll
        for (int ki = 0; ki < 4; ki++) {
            unsigned af[4][4], bf[4][2];
            #pragma unroll
            for (int mi = 0; mi < 4; mi++) {
                uint4 t = *(const uint4*)&As[flatA(ki, wm * 4 + mi, lane, 0)];
                af[mi][0] = t.x; af[mi][1] = t.y; af[mi][2] = t.z; af[mi][3] = t.w;
            }
            #pragma unroll
            for (int ni = 0; ni < 4; ni++) {
                uint2 t = *(const uint2*)&Bs[flatB(ki, wn * 4 + ni, lane, 0)];
                bf[ni][0] = t.x; bf[ni][1] = t.y;
            }
            #pragma unroll
            for (int mi = 0; mi < 4; mi++)
                #pragma unroll
                for (int ni = 0; ni < 4; ni++)
                    asm volatile(
                        "mma.sync.aligned.m16n8k8.row.col.f32.tf32.tf32.f32 "
                        "{%0,%1,%2,%3}, {%4,%5,%6,%7}, {%8,%9}, {%0,%1,%2,%3};"
                        : "+f"(acc[mi][ni][0]), "+f"(acc[mi][ni][1]),
                          "+f"(acc[mi][ni][2]), "+f"(acc[mi][ni][3])
                        : "r"(af[mi][0]), "r"(af[mi][1]), "r"(af[mi][2]), "r"(af[mi][3]),
                          "r"(bf[ni][0]), "r"(bf[ni][1]));
        }
        __syncthreads();
    }

    // ---- epilogue: bias + store (optionally scattered) ----
    float* Ydst = SCATTER ? Y : g_qkv;
    #pragma unroll
    for (int mi = 0; mi < 4; mi++) {
        int mrow = (wm * 4 + mi) * 16 + (lane >> 2);   // local row 0..127
        #pragma unroll
        for (int half = 0; half < 2; half++) {
            int ml = mrow + half * 8;
            size_t ob = SCATTER ? (size_t)outBase[ml] : (size_t)(m0 + ml) * N;
            #pragma unroll
            for (int ni = 0; ni < 4; ni++) {
                int n = n0 + (wn * 4 + ni) * 8 + (lane & 3) * 2;
                float2 b2 = *(const float2*)(bias + n);
                float2 val;
                val.x = acc[mi][ni][half * 2 + 0] + b2.x;
                val.y = acc[mi][ni][half * 2 + 1] + b2.y;
                *(float2*)(Ydst + ob + n) = val;
            }
        }
    }
}

// One block per (head, window). 64 threads; thread t owns score row t.
__global__ __launch_bounds__(64) void attn_kernel()
{
    const int h = blockIdx.x;   // 0..11
    const int w = blockIdx.y;   // 0..1023
    const int t = threadIdx.x;  // 0..63

    __shared__ float ks[64][33];
    __shared__ float vs[64][33];
    __shared__ float sc[64][65];

    const float* base = g_qkv + (size_t)w * 64 * NQKV;
    const int qo = h * 32;
    const int ko = 384 + h * 32;
    const int vo = 768 + h * 32;

    for (int e = t; e < 64 * 32; e += 64) {
        int row = e >> 5, d = e & 31;
        ks[row][d] = base[row * NQKV + ko + d];
        vs[row][d] = base[row * NQKV + vo + d];
    }

    float qr[32];
    #pragma unroll
    for (int d = 0; d < 32; d += 4) {
        float4 q4 = *(const float4*)(base + t * NQKV + qo + d);
        qr[d] = q4.x; qr[d+1] = q4.y; qr[d+2] = q4.z; qr[d+3] = q4.w;
    }
    __syncthreads();

    for (int j = 0; j < 64; j++) {
        float s = 0.f;
        #pragma unroll
        for (int d = 0; d < 32; d++) s = fmaf(qr[d], ks[j][d], s);
        sc[t][j] = s;
    }
    __syncthreads();

    const float scale = 0.17677669529663687f;   // 1/sqrt(32)
    float mx = -1e30f;
    for (int j = 0; j < 64; j++) mx = fmaxf(mx, sc[t][j]);
    float sum = 0.f;
    for (int j = 0; j < 64; j++) {
        float p = __expf((sc[t][j] - mx) * scale);
        sc[t][j] = p;
        sum += p;
    }
    float inv = 1.f / sum;

    float acc[32];
    #pragma unroll
    for (int d = 0; d < 32; d++) acc[d] = 0.f;
    for (int j = 0; j < 64; j++) {
        float p = sc[t][j];
        #pragma unroll
        for (int d = 0; d < 32; d++) acc[d] = fmaf(p, vs[j][d], acc[d]);
    }

    #pragma unroll
    for (int d = 0; d < 32; d++) ks[t][d] = acc[d] * inv;
    __syncthreads();

    float* obase = g_att + (size_t)w * 64 * C_IN + h * 32;
    for (int e = t; e < 64 * 32; e += 64) {
        int row = e >> 5, d = e & 31;
        obase[row * C_IN + d] = ks[row][d];
    }
}

extern "C" void kernel_launch(void* const* d_in, const int* in_sizes, int n_in,
                              void* d_out, int out_size)
{
    const float* x      = (const float*)d_in[0];
    const float* w_qkv  = (const float*)d_in[1];
    const float* b_qkv  = (const float*)d_in[2];
    const float* w_proj = (const float*)d_in[3];
    const float* b_proj = (const float*)d_in[4];
    float* out = (float*)d_out;

    // Stage 1: gathered QKV GEMM  (65536 x 1152 x 384), tf32 tensor cores
    gemm_tc<NQKV, true, false><<<dim3(9, 512), 256>>>(x, w_qkv, b_qkv, out);

    // Stage 2: window attention
    attn_kernel<<<dim3(12, 1024), 64>>>();

    // Stage 3: proj GEMM with scatter (65536 x 384 x 384), tf32 tensor cores
    gemm_tc<C_IN, false, true><<<dim3(3, 512), 256>>>(x, w_proj, b_proj, out);
}